// round 7
// baseline (speedup 1.0000x reference)
#include <cuda_runtime.h>
#include <math.h>

#define BSZ 4
#define SEQ 256
#define DM  128
#define NH  8
#define DK  16
#define NKN 16
#define NEGF (-1e32f)

// fast helpers: exp via MUFU.EX2, sqrt via MUFU.RSQ (guarded at 0)
__device__ __forceinline__ float fexp(float x){ return __expf(x); }
__device__ __forceinline__ float fsqrt0(float x){ return (x > 0.f) ? x*__frsqrt_rn(x) : 0.f; }

// ---------------- scratch ----------------
__device__ float g_Q1[BSZ*SEQ*DM];
__device__ float g_V1[BSZ*SEQ*DM];
__device__ float g_A1[BSZ*SEQ*DM];
__device__ float g_K2[BSZ*SEQ*DM];
__device__ float g_V2[BSZ*SEQ*DM];
__device__ float g_Q2[NKN*DM];
__device__ float g_A2[BSZ*NKN*SEQ*DM];
__device__ float g_WT[7*DM*DM];   // 0:b1_Wq 1:b1_Wv 2:b1_Wo 3:b4_Wq 4:b4_Wk 5:b4_Wv 6:b4_Wo

// ---------------- warp helpers ----------------
__device__ __forceinline__ float wmax(float v){
    #pragma unroll
    for (int o=16;o>0;o>>=1) v = fmaxf(v, __shfl_xor_sync(0xffffffffu, v, o));
    return v;
}
__device__ __forceinline__ float wsum(float v){
    #pragma unroll
    for (int o=16;o>0;o>>=1) v += __shfl_xor_sync(0xffffffffu, v, o);
    return v;
}
__device__ __forceinline__ float wscan_incl(float x, int lane){
    #pragma unroll
    for (int o=1;o<32;o<<=1){
        float y = __shfl_up_sync(0xffffffffu, x, o);
        if (lane >= o) x += y;
    }
    return x;
}

// ---------------- weight transpose ----------------
struct WPtrs { const float* w[7]; };

__global__ void wt_kernel(WPtrs ws, float* __restrict__ WT)
{
    __shared__ float s[32][33];
    const int m  = blockIdx.y;
    const int bx = blockIdx.x;
    const int r0 = (bx & 3) * 32, c0 = (bx >> 2) * 32;
    const int tx = threadIdx.x, ty = threadIdx.y;   // 32 x 8
    const float* src = ws.w[m];
    float* dst = WT + m*DM*DM;

    #pragma unroll
    for (int i=0;i<4;i++)
        s[ty+8*i][tx] = src[(r0+ty+8*i)*DM + c0+tx];
    __syncthreads();
    #pragma unroll
    for (int i=0;i<4;i++)
        dst[(c0+ty+8*i)*DM + r0+tx] = s[tx][ty+8*i];
}

// ---------------- batched projection: Y = X @ W^T + b (4 rows/block) ----------------
struct ProjSet { const float* X; int wsel; const float* B; float* Y; int M; };

__global__ void proj4_kernel(ProjSet s0, ProjSet s1, ProjSet s2, ProjSet s3,
                             const float* __restrict__ WTbase)
{
    __shared__ float Ash[4*DM];
    ProjSet s;
    switch (blockIdx.y){
        case 0: s = s0; break;
        case 1: s = s1; break;
        case 2: s = s2; break;
        default: s = s3; break;
    }
    const int t = threadIdx.x;             // 128
    const int row0 = blockIdx.x * 4;
    if (row0 >= s.M) return;

    const float* __restrict__ WT = WTbase + s.wsel*DM*DM;

    #pragma unroll
    for (int r=0;r<4;r++){
        int row = row0 + r;
        Ash[r*DM + t] = (row < s.M) ? s.X[(size_t)row*DM + t] : 0.f;
    }
    __syncthreads();

    float acc[4] = {0.f,0.f,0.f,0.f};
    for (int k=0;k<DM;k+=8){
        float w0 = WT[(k+0)*DM + t];
        float w1 = WT[(k+1)*DM + t];
        float w2 = WT[(k+2)*DM + t];
        float w3 = WT[(k+3)*DM + t];
        float w4 = WT[(k+4)*DM + t];
        float w5 = WT[(k+5)*DM + t];
        float w6 = WT[(k+6)*DM + t];
        float w7 = WT[(k+7)*DM + t];
        #pragma unroll
        for (int r=0;r<4;r++){
            float4 a0 = *(const float4*)&Ash[r*DM + k];
            float4 a1 = *(const float4*)&Ash[r*DM + k + 4];
            acc[r] += a0.x*w0 + a0.y*w1 + a0.z*w2 + a0.w*w3
                    + a1.x*w4 + a1.y*w5 + a1.z*w6 + a1.w*w7;
        }
    }
    const float bv = s.B[t];
    #pragma unroll
    for (int r=0;r<4;r++){
        int row = row0 + r;
        if (row < s.M) s.Y[(size_t)row*DM + t] = acc[r] + bv;
    }
}

// ---------------- layer-1 attention ----------------
// grid: (16 chunks, 32 b*h), block 256, 2 rows per warp.
__global__ void attn1_kernel(const float* __restrict__ Q1, const float* __restrict__ V1,
                             const float* __restrict__ gamma, float* __restrict__ qsc,
                             float* __restrict__ A1)
{
    __shared__ __align__(16) float KshT[DK*SEQ];   // [d][j]
    __shared__ __align__(16) float Vsh[SEQ*20];    // [j][20]
    __shared__ float orow[8][16];

    const int chunk = blockIdx.x;      // 0..15
    const int bh    = blockIdx.y;      // 0..31
    const int b = bh >> 3, h = bh & 7;
    const int tid = threadIdx.x, lane = tid & 31, w = tid >> 5;

    for (int idx=tid; idx<SEQ*DK; idx+=256){
        int j = idx >> 4, d = idx & 15;
        size_t g = (size_t)(b*SEQ + j)*DM + h*DK + d;
        KshT[d*SEQ + j] = Q1[g];
        Vsh[j*20 + d]   = V1[g];
    }
    __syncthreads();

    const float gdec = fabsf(gamma[h]);

    for (int r=0;r<2;r++){
        const int i = (chunk*8 + w) + 128*r;
        const int last = i, tmax = last >> 5;

        float q[DK];
        #pragma unroll
        for (int d=0;d<DK;d++) q[d] = KshT[d*SEQ + i];

        float sc[8], e[8], cum[8], p2[8];

        #pragma unroll
        for (int t=0;t<8;t++) if (t<=tmax){
            int j = t*32 + lane;
            float s = 0.f;
            #pragma unroll
            for (int d=0;d<DK;d++) s += q[d]*KshT[d*SEQ + j];
            sc[t] = s * 0.25f;
        }
        float m1 = NEGF;
        #pragma unroll
        for (int t=0;t<8;t++) if (t<=tmax){
            int j = t*32 + lane;
            m1 = fmaxf(m1, (j<=last) ? sc[t] : NEGF);
        }
        m1 = wmax(m1);
        float sum1 = 0.f;
        #pragma unroll
        for (int t=0;t<8;t++) if (t<=tmax){
            int j = t*32 + lane;
            float ev = (j<=last) ? fexp(sc[t]-m1) : 0.f;
            e[t] = ev; sum1 += ev;
        }
        sum1 = wsum(sum1);
        float carry = 0.f;
        #pragma unroll
        for (int t=0;t<8;t++) if (t<=tmax){
            float x = wscan_incl(e[t], lane);
            cum[t] = x + carry;
            carry += __shfl_sync(0xffffffffu, x, 31);
        }
        const float Te = carry;
        const float inv1 = 1.0f / sum1;

        float m2 = NEGF;
        #pragma unroll
        for (int t=0;t<8;t++) if (t<=tmax){
            int j = t*32 + lane;
            float rem = fmaxf((Te - cum[t]) * inv1, 0.f);
            float pos = fabsf((float)(i - j));
            float dist = fsqrt0(rem * pos);
            float eff = fexp(-gdec * dist);
            eff = fminf(fmaxf(eff, 1e-5f), 1e5f);
            float v = sc[t] * eff;
            e[t] = v;
            m2 = fmaxf(m2, (j<=last) ? v : NEGF);
        }
        m2 = wmax(m2);
        float sum2 = 0.f;
        #pragma unroll
        for (int t=0;t<8;t++) if (t<=tmax){
            int j = t*32 + lane;
            float e2 = (j<=last) ? fexp(e[t]-m2) : 0.f;
            e[t] = e2; sum2 += e2;
        }
        sum2 = wsum(sum2);
        const float inv2 = 1.0f / sum2;
        #pragma unroll
        for (int t=0;t<8;t++) p2[t] = (t<=tmax) ? e[t]*inv2 : 0.f;

        float* qrow = qsc + ((size_t)(b*NH + h)*SEQ + i)*SEQ;
        #pragma unroll
        for (int t=0;t<8;t++) qrow[t*32 + lane] = p2[t];

        float o[16];
        #pragma unroll
        for (int d=0;d<16;d++) o[d] = 0.f;
        #pragma unroll
        for (int t=0;t<8;t++) if (t<=tmax){
            int j = t*32 + lane;
            float p = p2[t];
            float4 v0 = *(const float4*)&Vsh[j*20 + 0];
            float4 v1 = *(const float4*)&Vsh[j*20 + 4];
            float4 v2 = *(const float4*)&Vsh[j*20 + 8];
            float4 v3 = *(const float4*)&Vsh[j*20 + 12];
            o[0]+=p*v0.x; o[1]+=p*v0.y; o[2]+=p*v0.z; o[3]+=p*v0.w;
            o[4]+=p*v1.x; o[5]+=p*v1.y; o[6]+=p*v1.z; o[7]+=p*v1.w;
            o[8]+=p*v2.x; o[9]+=p*v2.y; o[10]+=p*v2.z; o[11]+=p*v2.w;
            o[12]+=p*v3.x; o[13]+=p*v3.y; o[14]+=p*v3.z; o[15]+=p*v3.w;
        }
        #pragma unroll
        for (int d=0;d<16;d++){
            float v = wsum(o[d]);
            if (lane == 0) orow[w][d] = v;
        }
        __syncwarp();
        if (lane < 16) A1[((size_t)(b*SEQ + i))*DM + h*DK + lane] = orow[w][lane];
        __syncwarp();
    }
}

// ---------------- fused: P = LN(q_emb + A1@Wo^T+bo); V2 = P@Wv^T+bv ----------------
// block 256 (split-k halves), 4 rows, grid 256.
__global__ void oln1_v2_kernel(const float* __restrict__ A1,
                               const float* __restrict__ WoT, const float* __restrict__ bo,
                               const float* __restrict__ Res,
                               const float* __restrict__ lg, const float* __restrict__ lb,
                               const float* __restrict__ WvT, const float* __restrict__ bv,
                               float* __restrict__ V2)
{
    __shared__ float Ash[4*DM];
    __shared__ float Ysh[4*DM];
    __shared__ float Red[4*DM];
    const int tid = threadIdx.x;
    const int t = tid & 127, half = tid >> 7;
    const int lane = tid & 31, wid = tid >> 5;
    const int row0 = blockIdx.x * 4;

    for (int idx=tid; idx<4*DM; idx+=256)
        Ash[idx] = A1[(size_t)row0*DM + idx];
    __syncthreads();

    float acc[4] = {0.f,0.f,0.f,0.f};
    {
        const int kbase = half*64;
        for (int kk=0;kk<64;kk+=8){
            int k = kbase + kk;
            float w0 = WoT[(k+0)*DM + t];
            float w1 = WoT[(k+1)*DM + t];
            float w2 = WoT[(k+2)*DM + t];
            float w3 = WoT[(k+3)*DM + t];
            float w4 = WoT[(k+4)*DM + t];
            float w5 = WoT[(k+5)*DM + t];
            float w6 = WoT[(k+6)*DM + t];
            float w7 = WoT[(k+7)*DM + t];
            #pragma unroll
            for (int r=0;r<4;r++){
                float4 a0 = *(const float4*)&Ash[r*DM + k];
                float4 a1 = *(const float4*)&Ash[r*DM + k + 4];
                acc[r] += a0.x*w0 + a0.y*w1 + a0.z*w2 + a0.w*w3
                        + a1.x*w4 + a1.y*w5 + a1.z*w6 + a1.w*w7;
            }
        }
    }
    if (half == 1){
        #pragma unroll
        for (int r=0;r<4;r++) Red[r*DM + t] = acc[r];
    }
    __syncthreads();
    if (half == 0){
        const float bov = bo[t];
        #pragma unroll
        for (int r=0;r<4;r++)
            Ysh[r*DM + t] = acc[r] + Red[r*DM + t] + bov + Res[(size_t)(row0+r)*DM + t];
    }
    __syncthreads();

    // LN: warps 0-3 handle rows 0-3
    if (wid < 4){
        const int r = wid;
        float4 v = *(const float4*)&Ysh[r*DM + lane*4];
        float sg = v.x+v.y+v.z+v.w;
        float sq = v.x*v.x+v.y*v.y+v.z*v.z+v.w*v.w;
        sg = wsum(sg); sq = wsum(sq);
        float mean = sg * (1.f/128.f);
        float var  = fmaxf(sq * (1.f/128.f) - mean*mean, 0.f);
        float rstd = rsqrtf(var + 1e-5f);
        float4 g = *(const float4*)&lg[lane*4];
        float4 bb = *(const float4*)&lb[lane*4];
        v.x = (v.x-mean)*rstd*g.x + bb.x;
        v.y = (v.y-mean)*rstd*g.y + bb.y;
        v.z = (v.z-mean)*rstd*g.z + bb.z;
        v.w = (v.w-mean)*rstd*g.w + bb.w;
        *(float4*)&Ysh[r*DM + lane*4] = v;
    }
    __syncthreads();

    #pragma unroll
    for (int r=0;r<4;r++) acc[r] = 0.f;
    {
        const int kbase = half*64;
        for (int kk=0;kk<64;kk+=8){
            int k = kbase + kk;
            float w0 = WvT[(k+0)*DM + t];
            float w1 = WvT[(k+1)*DM + t];
            float w2 = WvT[(k+2)*DM + t];
            float w3 = WvT[(k+3)*DM + t];
            float w4 = WvT[(k+4)*DM + t];
            float w5 = WvT[(k+5)*DM + t];
            float w6 = WvT[(k+6)*DM + t];
            float w7 = WvT[(k+7)*DM + t];
            #pragma unroll
            for (int r=0;r<4;r++){
                float4 a0 = *(const float4*)&Ysh[r*DM + k];
                float4 a1 = *(const float4*)&Ysh[r*DM + k + 4];
                acc[r] += a0.x*w0 + a0.y*w1 + a0.z*w2 + a0.w*w3
                        + a1.x*w4 + a1.y*w5 + a1.z*w6 + a1.w*w7;
            }
        }
    }
    __syncthreads();
    if (half == 1){
        #pragma unroll
        for (int r=0;r<4;r++) Red[r*DM + t] = acc[r];
    }
    __syncthreads();
    if (half == 0){
        const float bvv = bv[t];
        #pragma unroll
        for (int r=0;r<4;r++)
            V2[(size_t)(row0+r)*DM + t] = acc[r] + Red[r*DM + t] + bvv;
    }
}

// ---------------- layer-2 attention ----------------
// grid (4 i-chunks, 512 b*n*h), block 256, 8 rows per warp.
__global__ void attn2_kernel(const float* __restrict__ K2, const float* __restrict__ V2,
                             const float* __restrict__ Q2, const float* __restrict__ gamma,
                             float* __restrict__ ksc, float* __restrict__ A2)
{
    __shared__ __align__(16) float KshT[DK*SEQ];
    __shared__ __align__(16) float Vsh[SEQ*20];
    __shared__ float ss[SEQ];
    __shared__ float Ce[SEQ];
    __shared__ float wred[8];
    __shared__ float orow[8][16];

    const int chunk = blockIdx.x;       // 0..3
    const int bid = blockIdx.y;         // 0..511
    const int b = bid >> 7, n = (bid >> 3) & 15, h = bid & 7;
    const int tid = threadIdx.x, lane = tid & 31, w = tid >> 5;

    for (int idx=tid; idx<SEQ*DK; idx+=256){
        int j = idx >> 4, d = idx & 15;
        size_t g = (size_t)(b*SEQ + j)*DM + h*DK + d;
        KshT[d*SEQ + j] = K2[g];
        Vsh[j*20 + d]   = V2[g];
    }
    __syncthreads();

    float q[DK];
    #pragma unroll
    for (int d=0;d<DK;d++) q[d] = Q2[n*DM + h*DK + d];

    float s = 0.f;
    #pragma unroll
    for (int d=0;d<DK;d++) s += q[d]*KshT[d*SEQ + tid];
    s *= 0.25f;
    ss[tid] = s;

    float m = wmax(s);
    if (lane == 0) wred[w] = m;
    __syncthreads();
    float bmax = wred[0];
    #pragma unroll
    for (int k=1;k<8;k++) bmax = fmaxf(bmax, wred[k]);
    float e = fexp(s - bmax);
    float x = wscan_incl(e, lane);
    __syncthreads();
    if (lane == 31) wred[w] = x;
    __syncthreads();
    float off = 0.f;
    for (int k=0;k<w;k++) off += wred[k];
    Ce[tid] = x + off;
    __syncthreads();

    const float gdec = fabsf(gamma[h]);

    for (int r=0;r<8;r++){
        const int i = (r*4 + chunk)*8 + w;
        float* krow = ksc + (((size_t)(b*NH + h)*SEQ + i)*NKN + n)*SEQ;
        if (i == 0){
            #pragma unroll
            for (int t=0;t<8;t++) krow[t*32 + lane] = 0.f;
            if (lane < 16) A2[((size_t)((b*NKN + n)*SEQ + 0))*DM + h*DK + lane] = 0.f;
            continue;
        }
        const int last = i - 1, tmax = last >> 5;
        const float invS = 1.0f / Ce[last];

        float sc2[8];
        float m2 = NEGF;
        #pragma unroll
        for (int t=0;t<8;t++) if (t<=tmax){
            int j = t*32 + lane;
            float rem = fmaxf(1.0f - Ce[j]*invS, 0.f);
            float pos = fabsf((float)(i - j));
            float dist = fsqrt0(rem * pos);
            float eff = fexp(-gdec * dist);
            eff = fminf(fmaxf(eff, 1e-5f), 1e5f);
            float v = ss[j] * eff;
            sc2[t] = v;
            m2 = fmaxf(m2, (j<=last) ? v : NEGF);
        }
        m2 = wmax(m2);
        float sum2 = 0.f;
        #pragma unroll
        for (int t=0;t<8;t++) if (t<=tmax){
            int j = t*32 + lane;
            float e2 = (j<=last) ? fexp(sc2[t]-m2) : 0.f;
            sc2[t] = e2; sum2 += e2;
        }
        sum2 = wsum(sum2);
        const float coef = fminf(sum2, 5.0f) / sum2;

        float o[16];
        #pragma unroll
        for (int d=0;d<16;d++) o[d] = 0.f;
        #pragma unroll
        for (int t=0;t<8;t++){
            float p = (t<=tmax) ? sc2[t]*coef : 0.f;
            krow[t*32 + lane] = p;
            if (t<=tmax){
                int j = t*32 + lane;
                float4 v0 = *(const float4*)&Vsh[j*20 + 0];
                float4 v1 = *(const float4*)&Vsh[j*20 + 4];
                float4 v2 = *(const float4*)&Vsh[j*20 + 8];
                float4 v3 = *(const float4*)&Vsh[j*20 + 12];
                o[0]+=p*v0.x; o[1]+=p*v0.y; o[2]+=p*v0.z; o[3]+=p*v0.w;
                o[4]+=p*v1.x; o[5]+=p*v1.y; o[6]+=p*v1.z; o[7]+=p*v1.w;
                o[8]+=p*v2.x; o[9]+=p*v2.y; o[10]+=p*v2.z; o[11]+=p*v2.w;
                o[12]+=p*v3.x; o[13]+=p*v3.y; o[14]+=p*v3.z; o[15]+=p*v3.w;
            }
        }
        #pragma unroll
        for (int d=0;d<16;d++){
            float v = wsum(o[d]);
            if (lane == 0) orow[w][d] = v;
        }
        __syncwarp();
        if (lane < 16) A2[((size_t)((b*NKN + n)*SEQ + i))*DM + h*DK + lane] = orow[w][lane];
        __syncwarp();
    }
}

// ---------------- out-proj + residual(know) + layernorm -> z (4 rows/block) ----------------
__global__ void outln2_kernel(const float* __restrict__ Ain, const float* __restrict__ WoT,
                              const float* __restrict__ bias, const float* __restrict__ Know,
                              const float* __restrict__ lg, const float* __restrict__ lb,
                              float* __restrict__ Z)
{
    __shared__ float Ash[4*DM];
    __shared__ float Ysh[4*DM];
    const int t = threadIdx.x, lane = t & 31, w = t >> 5;
    const int row0 = blockIdx.x * 4;
    const int nn = (row0 >> 8) & 15;     // constant within block (4 | 256)
    const int bI = row0 >> 12;

    #pragma unroll
    for (int r=0;r<4;r++)
        Ash[r*DM + t] = Ain[(size_t)(row0+r)*DM + t];
    __syncthreads();

    float acc[4] = {0.f,0.f,0.f,0.f};
    for (int k=0;k<DM;k+=8){
        float w0 = WoT[(k+0)*DM + t];
        float w1 = WoT[(k+1)*DM + t];
        float w2 = WoT[(k+2)*DM + t];
        float w3 = WoT[(k+3)*DM + t];
        float w4 = WoT[(k+4)*DM + t];
        float w5 = WoT[(k+5)*DM + t];
        float w6 = WoT[(k+6)*DM + t];
        float w7 = WoT[(k+7)*DM + t];
        #pragma unroll
        for (int r=0;r<4;r++){
            float4 a0 = *(const float4*)&Ash[r*DM + k];
            float4 a1 = *(const float4*)&Ash[r*DM + k + 4];
            acc[r] += a0.x*w0 + a0.y*w1 + a0.z*w2 + a0.w*w3
                    + a1.x*w4 + a1.y*w5 + a1.z*w6 + a1.w*w7;
        }
    }
    {
        const float bv = bias[t], kn = Know[nn*DM + t];
        #pragma unroll
        for (int r=0;r<4;r++)
            Ysh[r*DM + t] = acc[r] + bv + kn;
    }
    __syncthreads();

    // LN: warp w handles row w (4 warps)
    {
        const int r = w;
        const int row = row0 + r;
        const int ii = row & 255;
        float4 v = *(const float4*)&Ysh[r*DM + lane*4];
        float sg = v.x+v.y+v.z+v.w;
        float sq = v.x*v.x+v.y*v.y+v.z*v.z+v.w*v.w;
        sg = wsum(sg); sq = wsum(sq);
        float mean = sg * (1.f/128.f);
        float var  = fmaxf(sq * (1.f/128.f) - mean*mean, 0.f);
        float rstd = rsqrtf(var + 1e-5f);
        float4 g = *(const float4*)&lg[lane*4];
        float4 bb = *(const float4*)&lb[lane*4];
        v.x = (v.x-mean)*rstd*g.x + bb.x;
        v.y = (v.y-mean)*rstd*g.y + bb.y;
        v.z = (v.z-mean)*rstd*g.z + bb.z;
        v.w = (v.w-mean)*rstd*g.w + bb.w;
        *(float4*)&Z[((size_t)(bI*SEQ + ii))*(NKN*DM) + nn*DM + lane*4] = v;
    }
}

// ---------------- launch ----------------
extern "C" void kernel_launch(void* const* d_in, const int* in_sizes, int n_in,
                              void* d_out, int out_size)
{
    const float* q_emb   = (const float*)d_in[0];
    const float* s_emb   = (const float*)d_in[1];
    const float* b1_Wq   = (const float*)d_in[3];
    const float* b1_bq   = (const float*)d_in[4];
    const float* b1_Wv   = (const float*)d_in[5];
    const float* b1_bv   = (const float*)d_in[6];
    const float* b1_Wo   = (const float*)d_in[7];
    const float* b1_bo   = (const float*)d_in[8];
    const float* b1_gam  = (const float*)d_in[9];
    const float* b1_lng  = (const float*)d_in[10];
    const float* b1_lnb  = (const float*)d_in[11];
    const float* b4_Wq   = (const float*)d_in[12];
    const float* b4_bq   = (const float*)d_in[13];
    const float* b4_Wk   = (const float*)d_in[14];
    const float* b4_bk   = (const float*)d_in[15];
    const float* b4_Wv   = (const float*)d_in[16];
    const float* b4_bv   = (const float*)d_in[17];
    const float* b4_Wo   = (const float*)d_in[18];
    const float* b4_bo   = (const float*)d_in[19];
    const float* b4_gam  = (const float*)d_in[20];
    const float* b4_lng  = (const float*)d_in[21];
    const float* b4_lnb  = (const float*)d_in[22];
    const float* know    = (const float*)d_in[23];

    float* out = (float*)d_out;
    float* z   = out;
    float* qsc = out + (size_t)BSZ*SEQ*NKN*DM;
    float* ksc = qsc + (size_t)BSZ*NH*SEQ*SEQ;

    float *pQ1,*pV1,*pA1,*pK2,*pV2,*pQ2,*pA2,*pWT;
    cudaGetSymbolAddress((void**)&pQ1, g_Q1);
    cudaGetSymbolAddress((void**)&pV1, g_V1);
    cudaGetSymbolAddress((void**)&pA1, g_A1);
    cudaGetSymbolAddress((void**)&pK2, g_K2);
    cudaGetSymbolAddress((void**)&pV2, g_V2);
    cudaGetSymbolAddress((void**)&pQ2, g_Q2);
    cudaGetSymbolAddress((void**)&pA2, g_A2);
    cudaGetSymbolAddress((void**)&pWT, g_WT);

    const int MROWS = BSZ*SEQ;  // 1024

    WPtrs wp;
    wp.w[0]=b1_Wq; wp.w[1]=b1_Wv; wp.w[2]=b1_Wo; wp.w[3]=b4_Wq;
    wp.w[4]=b4_Wk; wp.w[5]=b4_Wv; wp.w[6]=b4_Wo;
    wt_kernel<<<dim3(16,7), dim3(32,8)>>>(wp, pWT);

    ProjSet sQ1 = { q_emb, 0, b1_bq, pQ1, MROWS };
    ProjSet sV1 = { s_emb, 1, b1_bv, pV1, MROWS };
    ProjSet sK2 = { q_emb, 4, b4_bk, pK2, MROWS };
    ProjSet sQ2 = { know,  3, b4_bq, pQ2, NKN   };
    proj4_kernel<<<dim3(MROWS/4, 4), 128>>>(sQ1, sV1, sK2, sQ2, pWT);

    attn1_kernel<<<dim3(16,32), 256>>>(pQ1, pV1, b1_gam, qsc, pA1);

    oln1_v2_kernel<<<MROWS/4, 256>>>(pA1, pWT + 2*DM*DM, b1_bo, q_emb,
                                     b1_lng, b1_lnb, pWT + 5*DM*DM, b4_bv, pV2);

    attn2_kernel<<<dim3(4,512), 256>>>(pK2, pV2, pQ2, b4_gam, ksc, pA2);

    outln2_kernel<<<(BSZ*NKN*SEQ)/4, 128>>>(pA2, pWT + 6*DM*DM, b4_bo, know,
                                            b4_lng, b4_lnb, z);
}

// round 9
// speedup vs baseline: 1.2913x; 1.2913x over previous
#include <cuda_runtime.h>
#include <math.h>

#define BSZ 4
#define SEQ 256
#define DM  128
#define NH  8
#define DK  16
#define NKN 16
#define NEGF (-1e32f)

// fast helpers
__device__ __forceinline__ float fexp(float x){ return __expf(x); }
__device__ __forceinline__ float fsqrt0(float x){ return (x > 0.f) ? x*__frsqrt_rn(x) : 0.f; }

// ---------------- scratch ----------------
__device__ float g_Q1[BSZ*SEQ*DM];
__device__ float g_V1[BSZ*SEQ*DM];
__device__ float g_A1[BSZ*SEQ*DM];
__device__ float g_K2[BSZ*SEQ*DM];
__device__ float g_V2[BSZ*SEQ*DM];
__device__ float g_Q2[NKN*DM];
__device__ float g_A2[BSZ*NKN*SEQ*DM];
__device__ float g_WT[7*DM*DM];   // 0:b1_Wq 1:b1_Wv 2:b1_Wo 3:b4_Wq 4:b4_Wk 5:b4_Wv 6:b4_Wo

// ---------------- warp helpers ----------------
__device__ __forceinline__ float wmax(float v){
    #pragma unroll
    for (int o=16;o>0;o>>=1) v = fmaxf(v, __shfl_xor_sync(0xffffffffu, v, o));
    return v;
}
__device__ __forceinline__ float wsum(float v){
    #pragma unroll
    for (int o=16;o>0;o>>=1) v += __shfl_xor_sync(0xffffffffu, v, o);
    return v;
}
__device__ __forceinline__ float wscan_incl(float x, int lane){
    #pragma unroll
    for (int o=1;o<32;o<<=1){
        float y = __shfl_up_sync(0xffffffffu, x, o);
        if (lane >= o) x += y;
    }
    return x;
}

// Reduce 16 per-lane partials across the warp via halving tree.
// Result: every lane holds the full sum for d = (lane>>1)&15
// (so even lane 2m holds o[m] -> coalesced 64B store from 16 even lanes).
__device__ __forceinline__ float treereduce16(const float* o, int lane){
    float a[8];
    #pragma unroll
    for (int k=0;k<8;k++){
        float send = (lane & 16) ? o[k]   : o[k+8];
        float keep = (lane & 16) ? o[k+8] : o[k];
        a[k] = keep + __shfl_xor_sync(0xffffffffu, send, 16);
    }
    float b[4];
    #pragma unroll
    for (int k=0;k<4;k++){
        float send = (lane & 8) ? a[k]   : a[k+4];
        float keep = (lane & 8) ? a[k+4] : a[k];
        b[k] = keep + __shfl_xor_sync(0xffffffffu, send, 8);
    }
    float c[2];
    #pragma unroll
    for (int k=0;k<2;k++){
        float send = (lane & 4) ? b[k]   : b[k+2];
        float keep = (lane & 4) ? b[k+2] : b[k];
        c[k] = keep + __shfl_xor_sync(0xffffffffu, send, 4);
    }
    float send = (lane & 2) ? c[0] : c[1];
    float keep = (lane & 2) ? c[1] : c[0];
    float d = keep + __shfl_xor_sync(0xffffffffu, send, 2);
    d += __shfl_xor_sync(0xffffffffu, d, 1);
    return d;
}

// ---------------- weight transpose ----------------
struct WPtrs { const float* w[7]; };

__global__ void wt_kernel(WPtrs ws, float* __restrict__ WT)
{
    __shared__ float s[32][33];
    const int m  = blockIdx.y;
    const int bx = blockIdx.x;
    const int r0 = (bx & 3) * 32, c0 = (bx >> 2) * 32;
    const int tx = threadIdx.x, ty = threadIdx.y;   // 32 x 8
    const float* src = ws.w[m];
    float* dst = WT + m*DM*DM;

    #pragma unroll
    for (int i=0;i<4;i++)
        s[ty+8*i][tx] = src[(r0+ty+8*i)*DM + c0+tx];
    __syncthreads();
    #pragma unroll
    for (int i=0;i<4;i++)
        dst[(c0+ty+8*i)*DM + r0+tx] = s[tx][ty+8*i];
}

// ---------------- batched projection (8 rows/block) ----------------
struct ProjSet { const float* X; int wsel; const float* B; float* Y; int M; };

__global__ void proj4_kernel(ProjSet s0, ProjSet s1, ProjSet s2, ProjSet s3,
                             const float* __restrict__ WTbase)
{
    __shared__ float Ash[8*DM];
    ProjSet s;
    switch (blockIdx.y){
        case 0: s = s0; break;
        case 1: s = s1; break;
        case 2: s = s2; break;
        default: s = s3; break;
    }
    const int t = threadIdx.x;             // 128
    const int row0 = blockIdx.x * 8;
    if (row0 >= s.M) return;

    const float* __restrict__ WT = WTbase + s.wsel*DM*DM;

    #pragma unroll
    for (int r=0;r<8;r++){
        int row = row0 + r;
        Ash[r*DM + t] = (row < s.M) ? s.X[(size_t)row*DM + t] : 0.f;
    }
    __syncthreads();

    float acc[8];
    #pragma unroll
    for (int r=0;r<8;r++) acc[r] = 0.f;

    for (int k=0;k<DM;k+=8){
        float w0 = WT[(k+0)*DM + t];
        float w1 = WT[(k+1)*DM + t];
        float w2 = WT[(k+2)*DM + t];
        float w3 = WT[(k+3)*DM + t];
        float w4 = WT[(k+4)*DM + t];
        float w5 = WT[(k+5)*DM + t];
        float w6 = WT[(k+6)*DM + t];
        float w7 = WT[(k+7)*DM + t];
        #pragma unroll
        for (int r=0;r<8;r++){
            float4 a0 = *(const float4*)&Ash[r*DM + k];
            float4 a1 = *(const float4*)&Ash[r*DM + k + 4];
            acc[r] += a0.x*w0 + a0.y*w1 + a0.z*w2 + a0.w*w3
                    + a1.x*w4 + a1.y*w5 + a1.z*w6 + a1.w*w7;
        }
    }
    const float bv = s.B[t];
    #pragma unroll
    for (int r=0;r<8;r++){
        int row = row0 + r;
        if (row < s.M) s.Y[(size_t)row*DM + t] = acc[r] + bv;
    }
}

// ---------------- layer-1 attention ----------------
// grid: (8 chunks, 32 b*h), block 256, 4 rows per warp.
__global__ void attn1_kernel(const float* __restrict__ Q1, const float* __restrict__ V1,
                             const float* __restrict__ gamma, float* __restrict__ qsc,
                             float* __restrict__ A1)
{
    __shared__ __align__(16) float KshT[DK*SEQ];   // [d][j]
    __shared__ __align__(16) float Vsh[SEQ*20];    // [j][20]

    const int chunk = blockIdx.x;      // 0..7
    const int bh    = blockIdx.y;      // 0..31
    const int b = bh >> 3, h = bh & 7;
    const int tid = threadIdx.x, lane = tid & 31, w = tid >> 5;

    for (int idx=tid; idx<SEQ*DK; idx+=256){
        int j = idx >> 4, d = idx & 15;
        size_t g = (size_t)(b*SEQ + j)*DM + h*DK + d;
        KshT[d*SEQ + j] = Q1[g];
        Vsh[j*20 + d]   = V1[g];
    }
    __syncthreads();

    const float gdec = fabsf(gamma[h]);

    for (int r=0;r<4;r++){
        const int i = (chunk*8 + w) + 64*r;
        const int last = i, tmax = last >> 5;

        float q[DK];
        #pragma unroll
        for (int d=0;d<DK;d++) q[d] = KshT[d*SEQ + i];

        float sc[8], e[8], cum[8];

        #pragma unroll
        for (int t=0;t<8;t++) if (t<=tmax){
            int j = t*32 + lane;
            float s = 0.f;
            #pragma unroll
            for (int d=0;d<DK;d++) s += q[d]*KshT[d*SEQ + j];
            sc[t] = s * 0.25f;
        }
        // softmax #1 (masked)
        float m1 = NEGF;
        #pragma unroll
        for (int t=0;t<8;t++) if (t<=tmax){
            int j = t*32 + lane;
            m1 = fmaxf(m1, (j<=last) ? sc[t] : NEGF);
        }
        m1 = wmax(m1);
        float sum1 = 0.f;
        #pragma unroll
        for (int t=0;t<8;t++) if (t<=tmax){
            int j = t*32 + lane;
            float ev = (j<=last) ? fexp(sc[t]-m1) : 0.f;
            e[t] = ev; sum1 += ev;
        }
        sum1 = wsum(sum1);
        float carry = 0.f;
        #pragma unroll
        for (int t=0;t<8;t++) if (t<=tmax){
            float x = wscan_incl(e[t], lane);
            cum[t] = x + carry;
            carry += __shfl_sync(0xffffffffu, x, 31);
        }
        const float Te = carry;
        const float inv1 = 1.0f / sum1;
        const float M = fmaxf(m1, 0.f);   // eff<=1 => sc*eff <= max(m1,0): safe fixed reference

        // single fused pass: effect + scores2 + exp
        float sum2 = 0.f;
        #pragma unroll
        for (int t=0;t<8;t++){
            if (t<=tmax){
                int j = t*32 + lane;
                float rem = fmaxf((Te - cum[t]) * inv1, 0.f);
                float dist = fsqrt0(rem * (float)(i - j));
                float eff = fmaxf(fexp(-gdec * dist), 1e-5f);
                float v = sc[t] * eff;
                float ee = (j<=last) ? fexp(v - M) : 0.f;
                e[t] = ee; sum2 += ee;
            } else e[t] = 0.f;
        }
        sum2 = wsum(sum2);
        const float inv2 = 1.0f / sum2;

        float* qrow = qsc + ((size_t)(b*NH + h)*SEQ + i)*SEQ;
        float o[16];
        #pragma unroll
        for (int d=0;d<16;d++) o[d] = 0.f;
        #pragma unroll
        for (int t=0;t<8;t++){
            float p = e[t]*inv2;
            qrow[t*32 + lane] = p;
            if (t<=tmax){
                int j = t*32 + lane;
                float4 v0 = *(const float4*)&Vsh[j*20 + 0];
                float4 v1 = *(const float4*)&Vsh[j*20 + 4];
                float4 v2 = *(const float4*)&Vsh[j*20 + 8];
                float4 v3 = *(const float4*)&Vsh[j*20 + 12];
                o[0]+=p*v0.x; o[1]+=p*v0.y; o[2]+=p*v0.z; o[3]+=p*v0.w;
                o[4]+=p*v1.x; o[5]+=p*v1.y; o[6]+=p*v1.z; o[7]+=p*v1.w;
                o[8]+=p*v2.x; o[9]+=p*v2.y; o[10]+=p*v2.z; o[11]+=p*v2.w;
                o[12]+=p*v3.x; o[13]+=p*v3.y; o[14]+=p*v3.z; o[15]+=p*v3.w;
            }
        }
        float od = treereduce16(o, lane);
        if (!(lane & 1))
            A1[((size_t)(b*SEQ + i))*DM + h*DK + ((lane>>1)&15)] = od;
    }
}

// ---------------- fused: P = LN(q_emb + A1@Wo^T+bo); V2 = P@Wv^T+bv ----------------
// block 256 (split-k halves), 8 rows, grid 128.
__global__ void oln1_v2_kernel(const float* __restrict__ A1,
                               const float* __restrict__ WoT, const float* __restrict__ bo,
                               const float* __restrict__ Res,
                               const float* __restrict__ lg, const float* __restrict__ lb,
                               const float* __restrict__ WvT, const float* __restrict__ bv,
                               float* __restrict__ V2)
{
    __shared__ float Ash[8*DM];
    __shared__ float Ysh[8*DM];
    __shared__ float Red[8*DM];
    const int tid = threadIdx.x;
    const int t = tid & 127, half = tid >> 7;
    const int lane = tid & 31, wid = tid >> 5;
    const int row0 = blockIdx.x * 8;

    for (int idx=tid; idx<8*DM; idx+=256)
        Ash[idx] = A1[(size_t)row0*DM + idx];
    __syncthreads();

    float acc[8];
    #pragma unroll
    for (int r=0;r<8;r++) acc[r] = 0.f;
    {
        const int kbase = half*64;
        for (int kk=0;kk<64;kk+=8){
            int k = kbase + kk;
            float w0 = WoT[(k+0)*DM + t];
            float w1 = WoT[(k+1)*DM + t];
            float w2 = WoT[(k+2)*DM + t];
            float w3 = WoT[(k+3)*DM + t];
            float w4 = WoT[(k+4)*DM + t];
            float w5 = WoT[(k+5)*DM + t];
            float w6 = WoT[(k+6)*DM + t];
            float w7 = WoT[(k+7)*DM + t];
            #pragma unroll
            for (int r=0;r<8;r++){
                float4 a0 = *(const float4*)&Ash[r*DM + k];
                float4 a1 = *(const float4*)&Ash[r*DM + k + 4];
                acc[r] += a0.x*w0 + a0.y*w1 + a0.z*w2 + a0.w*w3
                        + a1.x*w4 + a1.y*w5 + a1.z*w6 + a1.w*w7;
            }
        }
    }
    if (half == 1){
        #pragma unroll
        for (int r=0;r<8;r++) Red[r*DM + t] = acc[r];
    }
    __syncthreads();
    if (half == 0){
        const float bov = bo[t];
        #pragma unroll
        for (int r=0;r<8;r++)
            Ysh[r*DM + t] = acc[r] + Red[r*DM + t] + bov + Res[(size_t)(row0+r)*DM + t];
    }
    __syncthreads();

    // LN per row: warp wid handles row wid (8 warps)
    {
        const int r = wid;
        float4 v = *(const float4*)&Ysh[r*DM + lane*4];
        float sg = v.x+v.y+v.z+v.w;
        float sq = v.x*v.x+v.y*v.y+v.z*v.z+v.w*v.w;
        sg = wsum(sg); sq = wsum(sq);
        float mean = sg * (1.f/128.f);
        float var  = fmaxf(sq * (1.f/128.f) - mean*mean, 0.f);
        float rstd = rsqrtf(var + 1e-5f);
        float4 g = *(const float4*)&lg[lane*4];
        float4 bb = *(const float4*)&lb[lane*4];
        v.x = (v.x-mean)*rstd*g.x + bb.x;
        v.y = (v.y-mean)*rstd*g.y + bb.y;
        v.z = (v.z-mean)*rstd*g.z + bb.z;
        v.w = (v.w-mean)*rstd*g.w + bb.w;
        *(float4*)&Ysh[r*DM + lane*4] = v;
    }
    __syncthreads();

    #pragma unroll
    for (int r=0;r<8;r++) acc[r] = 0.f;
    {
        const int kbase = half*64;
        for (int kk=0;kk<64;kk+=8){
            int k = kbase + kk;
            float w0 = WvT[(k+0)*DM + t];
            float w1 = WvT[(k+1)*DM + t];
            float w2 = WvT[(k+2)*DM + t];
            float w3 = WvT[(k+3)*DM + t];
            float w4 = WvT[(k+4)*DM + t];
            float w5 = WvT[(k+5)*DM + t];
            float w6 = WvT[(k+6)*DM + t];
            float w7 = WvT[(k+7)*DM + t];
            #pragma unroll
            for (int r=0;r<8;r++){
                float4 a0 = *(const float4*)&Ysh[r*DM + k];
                float4 a1 = *(const float4*)&Ysh[r*DM + k + 4];
                acc[r] += a0.x*w0 + a0.y*w1 + a0.z*w2 + a0.w*w3
                        + a1.x*w4 + a1.y*w5 + a1.z*w6 + a1.w*w7;
            }
        }
    }
    __syncthreads();
    if (half == 1){
        #pragma unroll
        for (int r=0;r<8;r++) Red[r*DM + t] = acc[r];
    }
    __syncthreads();
    if (half == 0){
        const float bvv = bv[t];
        #pragma unroll
        for (int r=0;r<8;r++)
            V2[(size_t)(row0+r)*DM + t] = acc[r] + Red[r*DM + t] + bvv;
    }
}

// ---------------- layer-2 attention ----------------
// grid 512 (b,n,h), block 256, 32 rows per warp.
__global__ void attn2_kernel(const float* __restrict__ K2, const float* __restrict__ V2,
                             const float* __restrict__ Q2, const float* __restrict__ gamma,
                             float* __restrict__ ksc, float* __restrict__ A2)
{
    __shared__ __align__(16) float KshT[DK*SEQ];
    __shared__ __align__(16) float Vsh[SEQ*20];
    __shared__ float ss[SEQ];
    __shared__ float Ce[SEQ];
    __shared__ float wred[8];

    const int bid = blockIdx.x;
    const int b = bid >> 7, n = (bid >> 3) & 15, h = bid & 7;
    const int tid = threadIdx.x, lane = tid & 31, w = tid >> 5;

    for (int idx=tid; idx<SEQ*DK; idx+=256){
        int j = idx >> 4, d = idx & 15;
        size_t g = (size_t)(b*SEQ + j)*DM + h*DK + d;
        KshT[d*SEQ + j] = K2[g];
        Vsh[j*20 + d]   = V2[g];
    }
    __syncthreads();

    float q[DK];
    #pragma unroll
    for (int d=0;d<DK;d++) q[d] = Q2[n*DM + h*DK + d];

    float s = 0.f;
    #pragma unroll
    for (int d=0;d<DK;d++) s += q[d]*KshT[d*SEQ + tid];
    s *= 0.25f;
    ss[tid] = s;

    float m = wmax(s);
    if (lane == 0) wred[w] = m;
    __syncthreads();
    float bmax = wred[0];
    #pragma unroll
    for (int k=1;k<8;k++) bmax = fmaxf(bmax, wred[k]);
    float e = fexp(s - bmax);
    float x = wscan_incl(e, lane);
    __syncthreads();
    if (lane == 31) wred[w] = x;
    __syncthreads();
    float off = 0.f;
    for (int k=0;k<w;k++) off += wred[k];
    Ce[tid] = x + off;
    __syncthreads();

    const float gdec = fabsf(gamma[h]);
    const float M2 = fmaxf(bmax, 0.f);   // ss*eff <= max(max ss, 0): safe fixed reference

    for (int r=0;r<32;r++){
        const int i = w + 8*r;
        float* krow = ksc + (((size_t)(b*NH + h)*SEQ + i)*NKN + n)*SEQ;
        if (i == 0){
            #pragma unroll
            for (int t=0;t<8;t++) krow[t*32 + lane] = 0.f;
            if (!(lane & 1))
                A2[((size_t)((b*NKN + n)*SEQ + 0))*DM + h*DK + ((lane>>1)&15)] = 0.f;
            continue;
        }
        const int last = i - 1, tmax = last >> 5;
        const float invS = 1.0f / Ce[last];

        float e2[8];
        float emax = 0.f, sum2 = 0.f;
        #pragma unroll
        for (int t=0;t<8;t++){
            if (t<=tmax){
                int j = t*32 + lane;
                float rem = fmaxf(1.0f - Ce[j]*invS, 0.f);
                float dist = fsqrt0(rem * (float)(i - j));
                float eff = fmaxf(fexp(-gdec * dist), 1e-5f);
                float v = ss[j] * eff;
                float ee = (j<=last) ? fexp(v - M2) : 0.f;
                e2[t] = ee;
                emax = fmaxf(emax, ee);
                sum2 += ee;
            } else e2[t] = 0.f;
        }
        emax = wmax(emax);
        sum2 = wsum(sum2);
        // maxout: p = e2/sum2 * min(sum2/emax, 5) = e2 * min(1/emax, 5/sum2)
        const float coef = fminf(1.0f/emax, 5.0f/sum2);

        float o[16];
        #pragma unroll
        for (int d=0;d<16;d++) o[d] = 0.f;
        #pragma unroll
        for (int t=0;t<8;t++){
            float p = e2[t]*coef;
            krow[t*32 + lane] = p;
            if (t<=tmax){
                int j = t*32 + lane;
                float4 v0 = *(const float4*)&Vsh[j*20 + 0];
                float4 v1 = *(const float4*)&Vsh[j*20 + 4];
                float4 v2 = *(const float4*)&Vsh[j*20 + 8];
                float4 v3 = *(const float4*)&Vsh[j*20 + 12];
                o[0]+=p*v0.x; o[1]+=p*v0.y; o[2]+=p*v0.z; o[3]+=p*v0.w;
                o[4]+=p*v1.x; o[5]+=p*v1.y; o[6]+=p*v1.z; o[7]+=p*v1.w;
                o[8]+=p*v2.x; o[9]+=p*v2.y; o[10]+=p*v2.z; o[11]+=p*v2.w;
                o[12]+=p*v3.x; o[13]+=p*v3.y; o[14]+=p*v3.z; o[15]+=p*v3.w;
            }
        }
        float od = treereduce16(o, lane);
        if (!(lane & 1))
            A2[((size_t)((b*NKN + n)*SEQ + i))*DM + h*DK + ((lane>>1)&15)] = od;
    }
}

// ---------------- out-proj + residual(know) + layernorm -> z ----------------
// 128 thr, 8 rows, grid 2048; warp-per-row LN (no per-row barriers).
__global__ void outln2_kernel(const float* __restrict__ Ain, const float* __restrict__ WoT,
                              const float* __restrict__ bias, const float* __restrict__ Know,
                              const float* __restrict__ lg, const float* __restrict__ lb,
                              float* __restrict__ Z)
{
    __shared__ float Ash[8*DM];
    __shared__ float Ysh[8*DM];
    const int t = threadIdx.x, lane = t & 31, w = t >> 5;
    const int row0 = blockIdx.x * 8;
    const int nn = (row0 >> 8) & 15;     // constant within block (8 | 256)
    const int bI = row0 >> 12;

    #pragma unroll
    for (int r=0;r<8;r++)
        Ash[r*DM + t] = Ain[(size_t)(row0+r)*DM + t];
    __syncthreads();

    float acc[8];
    #pragma unroll
    for (int r=0;r<8;r++) acc[r] = 0.f;
    for (int k=0;k<DM;k+=8){
        float w0 = WoT[(k+0)*DM + t];
        float w1 = WoT[(k+1)*DM + t];
        float w2 = WoT[(k+2)*DM + t];
        float w3 = WoT[(k+3)*DM + t];
        float w4 = WoT[(k+4)*DM + t];
        float w5 = WoT[(k+5)*DM + t];
        float w6 = WoT[(k+6)*DM + t];
        float w7 = WoT[(k+7)*DM + t];
        #pragma unroll
        for (int r=0;r<8;r++){
            float4 a0 = *(const float4*)&Ash[r*DM + k];
            float4 a1 = *(const float4*)&Ash[r*DM + k + 4];
            acc[r] += a0.x*w0 + a0.y*w1 + a0.z*w2 + a0.w*w3
                    + a1.x*w4 + a1.y*w5 + a1.z*w6 + a1.w*w7;
        }
    }
    {
        const float bv = bias[t], kn = Know[nn*DM + t];
        #pragma unroll
        for (int r=0;r<8;r++)
            Ysh[r*DM + t] = acc[r] + bv + kn;
    }
    __syncthreads();

    // 4 warps x 2 rows each, warp-local LN, direct vectorized store
    #pragma unroll
    for (int rr=0; rr<2; rr++){
        const int r = w + rr*4;
        const int row = row0 + r;
        const int ii = row & 255;
        float4 v = *(const float4*)&Ysh[r*DM + lane*4];
        float sg = v.x+v.y+v.z+v.w;
        float sq = v.x*v.x+v.y*v.y+v.z*v.z+v.w*v.w;
        sg = wsum(sg); sq = wsum(sq);
        float mean = sg * (1.f/128.f);
        float var  = fmaxf(sq * (1.f/128.f) - mean*mean, 0.f);
        float rstd = rsqrtf(var + 1e-5f);
        float4 g = *(const float4*)&lg[lane*4];
        float4 bb = *(const float4*)&lb[lane*4];
        v.x = (v.x-mean)*rstd*g.x + bb.x;
        v.y = (v.y-mean)*rstd*g.y + bb.y;
        v.z = (v.z-mean)*rstd*g.z + bb.z;
        v.w = (v.w-mean)*rstd*g.w + bb.w;
        *(float4*)&Z[((size_t)(bI*SEQ + ii))*(NKN*DM) + nn*DM + lane*4] = v;
    }
}

// ---------------- launch ----------------
extern "C" void kernel_launch(void* const* d_in, const int* in_sizes, int n_in,
                              void* d_out, int out_size)
{
    const float* q_emb   = (const float*)d_in[0];
    const float* s_emb   = (const float*)d_in[1];
    const float* b1_Wq   = (const float*)d_in[3];
    const float* b1_bq   = (const float*)d_in[4];
    const float* b1_Wv   = (const float*)d_in[5];
    const float* b1_bv   = (const float*)d_in[6];
    const float* b1_Wo   = (const float*)d_in[7];
    const float* b1_bo   = (const float*)d_in[8];
    const float* b1_gam  = (const float*)d_in[9];
    const float* b1_lng  = (const float*)d_in[10];
    const float* b1_lnb  = (const float*)d_in[11];
    const float* b4_Wq   = (const float*)d_in[12];
    const float* b4_bq   = (const float*)d_in[13];
    const float* b4_Wk   = (const float*)d_in[14];
    const float* b4_bk   = (const float*)d_in[15];
    const float* b4_Wv   = (const float*)d_in[16];
    const float* b4_bv   = (const float*)d_in[17];
    const float* b4_Wo   = (const float*)d_in[18];
    const float* b4_bo   = (const float*)d_in[19];
    const float* b4_gam  = (const float*)d_in[20];
    const float* b4_lng  = (const float*)d_in[21];
    const float* b4_lnb  = (const float*)d_in[22];
    const float* know    = (const float*)d_in[23];

    float* out = (float*)d_out;
    float* z   = out;
    float* qsc = out + (size_t)BSZ*SEQ*NKN*DM;
    float* ksc = qsc + (size_t)BSZ*NH*SEQ*SEQ;

    float *pQ1,*pV1,*pA1,*pK2,*pV2,*pQ2,*pA2,*pWT;
    cudaGetSymbolAddress((void**)&pQ1, g_Q1);
    cudaGetSymbolAddress((void**)&pV1, g_V1);
    cudaGetSymbolAddress((void**)&pA1, g_A1);
    cudaGetSymbolAddress((void**)&pK2, g_K2);
    cudaGetSymbolAddress((void**)&pV2, g_V2);
    cudaGetSymbolAddress((void**)&pQ2, g_Q2);
    cudaGetSymbolAddress((void**)&pA2, g_A2);
    cudaGetSymbolAddress((void**)&pWT, g_WT);

    const int MROWS = BSZ*SEQ;  // 1024

    WPtrs wp;
    wp.w[0]=b1_Wq; wp.w[1]=b1_Wv; wp.w[2]=b1_Wo; wp.w[3]=b4_Wq;
    wp.w[4]=b4_Wk; wp.w[5]=b4_Wv; wp.w[6]=b4_Wo;
    wt_kernel<<<dim3(16,7), dim3(32,8)>>>(wp, pWT);

    ProjSet sQ1 = { q_emb, 0, b1_bq, pQ1, MROWS };
    ProjSet sV1 = { s_emb, 1, b1_bv, pV1, MROWS };
    ProjSet sK2 = { q_emb, 4, b4_bk, pK2, MROWS };
    ProjSet sQ2 = { know,  3, b4_bq, pQ2, NKN   };
    proj4_kernel<<<dim3(MROWS/8, 4), 128>>>(sQ1, sV1, sK2, sQ2, pWT);

    attn1_kernel<<<dim3(8,32), 256>>>(pQ1, pV1, b1_gam, qsc, pA1);

    oln1_v2_kernel<<<MROWS/8, 256>>>(pA1, pWT + 2*DM*DM, b1_bo, q_emb,
                                     b1_lng, b1_lnb, pWT + 5*DM*DM, b4_bv, pV2);

    attn2_kernel<<<512, 256>>>(pK2, pV2, pQ2, b4_gam, ksc, pA2);

    outln2_kernel<<<(BSZ*NKN*SEQ)/8, 128>>>(pA2, pWT + 6*DM*DM, b4_bo, know,
                                            b4_lng, b4_lnb, z);
}